// round 2
// baseline (speedup 1.0000x reference)
#include <cuda_runtime.h>
#include <cuda_bf16.h>
#include <math.h>

// Problem constants
#define BB 2
#define SS 2048
#define DD 1024
#define HH 16
#define DH 64
#define MM (BB * SS)   // 4096 rows for GEMMs

// Scratch (device globals: allocation-free rule)
__device__ float g_Q[(size_t)BB * SS * DD];
__device__ float g_K[(size_t)BB * SS * DD];
__device__ float g_V[(size_t)BB * SS * DD];
__device__ float g_AO[(size_t)BB * SS * DD];

// ---------------------------------------------------------------------------
// SGEMM: C[M,N] = A[M,K] @ W[K,N] + bias[N]
// 128x128 tile, BK=8, 256 threads, 8x8 micro-tile split as 2x(4)+2x(4)
// ---------------------------------------------------------------------------
__global__ __launch_bounds__(256) void gemm_bias_kernel(
    const float* __restrict__ A, const float* __restrict__ W,
    const float* __restrict__ bias, float* __restrict__ C,
    int M, int N, int K)
{
    __shared__ float As[8][128];
    __shared__ float Bs[8][128];

    const int tid = threadIdx.x;
    const int tx = tid & 15;        // 0..15
    const int ty = tid >> 4;        // 0..15
    const int blockRow = blockIdx.y * 128;
    const int blockCol = blockIdx.x * 128;

    // A-load mapping: 128 rows x 8 cols, thread -> (row, 4 cols)
    const int arow = tid >> 1;            // 0..127
    const int acol = (tid & 1) * 4;       // 0 or 4
    // B-load mapping: 8 rows x 128 cols
    const int brow = tid >> 5;            // 0..7
    const int bcol = (tid & 31) * 4;      // 0..124

    float acc[8][8];
#pragma unroll
    for (int i = 0; i < 8; i++)
#pragma unroll
        for (int j = 0; j < 8; j++) acc[i][j] = 0.0f;

    const int r0 = ty * 4;       // rows r0..r0+3 and 64+r0..64+r0+3
    const int c0 = tx * 4;       // cols c0..c0+3 and 64+c0..64+c0+3

    for (int k0 = 0; k0 < K; k0 += 8) {
        // Load A tile (transpose into As[k][m])
        float4 av = *reinterpret_cast<const float4*>(
            &A[(size_t)(blockRow + arow) * K + k0 + acol]);
        As[acol + 0][arow] = av.x;
        As[acol + 1][arow] = av.y;
        As[acol + 2][arow] = av.z;
        As[acol + 3][arow] = av.w;
        // Load B tile (direct)
        *reinterpret_cast<float4*>(&Bs[brow][bcol]) =
            *reinterpret_cast<const float4*>(
                &W[(size_t)(k0 + brow) * N + blockCol + bcol]);
        __syncthreads();

#pragma unroll
        for (int kk = 0; kk < 8; kk++) {
            float4 a0 = *reinterpret_cast<const float4*>(&As[kk][r0]);
            float4 a1 = *reinterpret_cast<const float4*>(&As[kk][64 + r0]);
            float4 b0 = *reinterpret_cast<const float4*>(&Bs[kk][c0]);
            float4 b1 = *reinterpret_cast<const float4*>(&Bs[kk][64 + c0]);
            float a[8] = {a0.x, a0.y, a0.z, a0.w, a1.x, a1.y, a1.z, a1.w};
            float b[8] = {b0.x, b0.y, b0.z, b0.w, b1.x, b1.y, b1.z, b1.w};
#pragma unroll
            for (int i = 0; i < 8; i++)
#pragma unroll
                for (int j = 0; j < 8; j++)
                    acc[i][j] = fmaf(a[i], b[j], acc[i][j]);
        }
        __syncthreads();
    }

    // Epilogue: 4 quadrants, float4 stores
#pragma unroll
    for (int ih = 0; ih < 2; ih++) {
#pragma unroll
        for (int i = 0; i < 4; i++) {
            int row = blockRow + ih * 64 + r0 + i;
#pragma unroll
            for (int jh = 0; jh < 2; jh++) {
                int col = blockCol + jh * 64 + c0;
                float4 bv = *reinterpret_cast<const float4*>(&bias[col]);
                float4 out;
                out.x = acc[ih * 4 + i][jh * 4 + 0] + bv.x;
                out.y = acc[ih * 4 + i][jh * 4 + 1] + bv.y;
                out.z = acc[ih * 4 + i][jh * 4 + 2] + bv.z;
                out.w = acc[ih * 4 + i][jh * 4 + 3] + bv.w;
                *reinterpret_cast<float4*>(&C[(size_t)row * N + col]) = out;
            }
        }
    }
}

// ---------------------------------------------------------------------------
// Flash attention: one thread per query row. 128 q-rows/block, 32-wide K tiles.
// Q/K/V layout [B,S,D] with head h occupying cols h*64..h*64+63.
// ---------------------------------------------------------------------------
#define BQ 128
#define BKT 32

__global__ __launch_bounds__(128) void attn_kernel(
    const float* __restrict__ Q, const float* __restrict__ K,
    const float* __restrict__ V, float* __restrict__ O)
{
    __shared__ float k_sh[BKT][DH];     // 8 KB
    __shared__ float v_sh[BKT][DH];     // 8 KB
    __shared__ float s_sh[BKT][BQ];     // 16 KB

    const int tid = threadIdx.x;
    const int bh = blockIdx.y;           // 0..B*H-1
    const int b = bh / HH;
    const int h = bh % HH;
    const int qs = blockIdx.x * BQ + tid;

    const float scale = 0.125f;          // 1/sqrt(64)

    // Load this thread's q row into registers (pre-scaled)
    float q[DH];
    {
        const float* qp = Q + (size_t)(b * SS + qs) * DD + h * DH;
#pragma unroll
        for (int d4 = 0; d4 < DH / 4; d4++) {
            float4 t = *reinterpret_cast<const float4*>(&qp[d4 * 4]);
            q[d4 * 4 + 0] = t.x * scale;
            q[d4 * 4 + 1] = t.y * scale;
            q[d4 * 4 + 2] = t.z * scale;
            q[d4 * 4 + 3] = t.w * scale;
        }
    }

    float o[DH];
#pragma unroll
    for (int d = 0; d < DH; d++) o[d] = 0.0f;
    float m = -1e30f;
    float l = 0.0f;

    for (int kt = 0; kt < SS / BKT; kt++) {
        __syncthreads();
        // Load K/V tiles: 2048 floats each, 128 threads x 4 float4
        const size_t base = (size_t)(b * SS + kt * BKT) * DD + h * DH;
#pragma unroll
        for (int i = 0; i < 4; i++) {
            int e = tid + i * 128;           // 0..511
            int kr = e >> 4;                 // 0..31
            int d4 = (e & 15) * 4;           // 0..60
            *reinterpret_cast<float4*>(&k_sh[kr][d4]) =
                *reinterpret_cast<const float4*>(&K[base + (size_t)kr * DD + d4]);
            *reinterpret_cast<float4*>(&v_sh[kr][d4]) =
                *reinterpret_cast<const float4*>(&V[base + (size_t)kr * DD + d4]);
        }
        __syncthreads();

        // Scores: s[kc] = q . k[kc]  (k_sh reads are warp-broadcast)
        for (int kc = 0; kc < BKT; kc++) {
            const float4* kv = reinterpret_cast<const float4*>(k_sh[kc]);
            float s = 0.0f;
#pragma unroll
            for (int d4 = 0; d4 < DH / 4; d4++) {
                float4 t = kv[d4];
                s = fmaf(q[d4 * 4 + 0], t.x, s);
                s = fmaf(q[d4 * 4 + 1], t.y, s);
                s = fmaf(q[d4 * 4 + 2], t.z, s);
                s = fmaf(q[d4 * 4 + 3], t.w, s);
            }
            s_sh[kc][tid] = s;
        }

        // Online softmax update
        float tm = m;
#pragma unroll
        for (int kc = 0; kc < BKT; kc++) tm = fmaxf(tm, s_sh[kc][tid]);
        float corr = __expf(m - tm);
        m = tm;
        l *= corr;
#pragma unroll
        for (int d = 0; d < DH; d++) o[d] *= corr;

        for (int kc = 0; kc < BKT; kc++) {
            float p = __expf(s_sh[kc][tid] - m);
            l += p;
            const float4* vv = reinterpret_cast<const float4*>(v_sh[kc]);
#pragma unroll
            for (int d4 = 0; d4 < DH / 4; d4++) {
                float4 t = vv[d4];
                o[d4 * 4 + 0] = fmaf(p, t.x, o[d4 * 4 + 0]);
                o[d4 * 4 + 1] = fmaf(p, t.y, o[d4 * 4 + 1]);
                o[d4 * 4 + 2] = fmaf(p, t.z, o[d4 * 4 + 2]);
                o[d4 * 4 + 3] = fmaf(p, t.w, o[d4 * 4 + 3]);
            }
        }
    }

    // Write normalized output
    const float inv = 1.0f / l;
    float* op = O + (size_t)(b * SS + qs) * DD + h * DH;
#pragma unroll
    for (int d4 = 0; d4 < DH / 4; d4++) {
        float4 t;
        t.x = o[d4 * 4 + 0] * inv;
        t.y = o[d4 * 4 + 1] * inv;
        t.z = o[d4 * 4 + 2] * inv;
        t.w = o[d4 * 4 + 3] * inv;
        *reinterpret_cast<float4*>(&op[d4 * 4]) = t;
    }
}

// ---------------------------------------------------------------------------
extern "C" void kernel_launch(void* const* d_in, const int* in_sizes, int n_in,
                              void* d_out, int out_size)
{
    const float* x  = (const float*)d_in[0];
    const float* Wq = (const float*)d_in[1];
    const float* bq = (const float*)d_in[2];
    const float* Wk = (const float*)d_in[3];
    const float* bk = (const float*)d_in[4];
    const float* Wv = (const float*)d_in[5];
    const float* bv = (const float*)d_in[6];
    const float* Wo = (const float*)d_in[7];
    const float* bo = (const float*)d_in[8];
    float* out = (float*)d_out;

    float *Q, *K, *V, *AO;
    cudaGetSymbolAddress((void**)&Q,  g_Q);
    cudaGetSymbolAddress((void**)&K,  g_K);
    cudaGetSymbolAddress((void**)&V,  g_V);
    cudaGetSymbolAddress((void**)&AO, g_AO);

    dim3 ggrid(DD / 128, MM / 128);   // (8, 32)
    gemm_bias_kernel<<<ggrid, 256>>>(x, Wq, bq, Q, MM, DD, DD);
    gemm_bias_kernel<<<ggrid, 256>>>(x, Wk, bk, K, MM, DD, DD);
    gemm_bias_kernel<<<ggrid, 256>>>(x, Wv, bv, V, MM, DD, DD);

    dim3 agrid(SS / BQ, BB * HH);     // (16, 32)
    attn_kernel<<<agrid, 128>>>(Q, K, V, AO);

    gemm_bias_kernel<<<ggrid, 256>>>(AO, Wo, bo, out, MM, DD, DD);
}